// round 15
// baseline (speedup 1.0000x reference)
#include <cuda_runtime.h>
#include <cstdint>

#define BB 8
#define DD 64
#define KK 32
#define HW 3136          // 56*56
#define LOG2E 1.4426950408889634f

// Scratch (allocation-free rule: __device__ global, rewritten every replay)
__device__ float g_EM[BB * DD];     // EM[b,d] (pre-divided by K)

__device__ __forceinline__ float fast_ex2(float x) {
    float y; asm("ex2.approx.ftz.f32 %0, %1;" : "=f"(y) : "f"(x)); return y;
}
__device__ __forceinline__ float fast_rcp(float x) {
    float y; asm("rcp.approx.ftz.f32 %0, %1;" : "=f"(y) : "f"(x)); return y;
}

// ───────────────────────── Kernel 1: main ─────────────────────────
// One CTA per (b,d) row, 256 threads, 2 n-values per thread-iter packed into
// f32x2 lanes. E[n] = x - (Σ_k e_k c_k)/(Σ_k e_k), e_k = exp2(A x² + B x + C).
// scale ≤ 0 ⇒ logits ≤ 0 ⇒ single-pass softmax safe.
// Per-k constants duplicated in smem as {A,A},{B,B},{C,C},{c,c}; re-fetched
// every n-iter via asm-volatile LDS so ptxas cannot hoist them into registers
// (R11/R12 showed that hoist collapses occupancy). Packed FFMA2/ADD2 halve
// fma-pipe pressure so MUFU (ex2) is the single binding pipe.
__global__ __launch_bounds__(256) void enc_main_kernel(
    const float* __restrict__ X,
    const float* __restrict__ codewords,
    const float* __restrict__ scale,
    float* __restrict__ outE)
{
    __shared__ float kc2[KK * 8];     // per k: A,A,B,B,C,C,c,c  (32 B)
    const int bd = blockIdx.x;
    const int d  = bd & (DD - 1);

    if (threadIdx.x < KK) {
        const int k = threadIdx.x;
        float c  = codewords[k * DD + d];
        float st = scale[k * DD + d] * LOG2E;
        float B  = -2.0f * st * c;
        float C  = st * c * c;
        float* p = kc2 + k * 8;
        p[0] = st; p[1] = st;
        p[2] = B;  p[3] = B;
        p[4] = C;  p[5] = C;
        p[6] = c;  p[7] = c;
    }
    __syncthreads();

    const uint32_t kc_base = (uint32_t)__cvta_generic_to_shared(kc2);

    const float2* __restrict__ xp2 = (const float2*)(X    + (size_t)bd * HW);
    float2* __restrict__       ep2 = (float2*)      (outE + (size_t)bd * HW);

    float local = 0.0f;
    for (int i = threadIdx.x; i < HW / 2; i += 256) {   // 1568 float2's
        const float2 xv = xp2[i];
        uint64_t x01, q01, den, cm;
        asm("mov.b64 %0, {%1,%2};" : "=l"(x01) : "f"(xv.x), "f"(xv.y));
        asm("mul.rn.f32x2 %0, %1, %1;" : "=l"(q01) : "l"(x01));
        asm("mov.b64 %0, {%1,%2};" : "=l"(den) : "f"(0.0f), "f"(0.0f));
        cm = den;
#pragma unroll
        for (int k = 0; k < KK; k++) {
            uint64_t AA, BBp, CC, cc;
            asm volatile("ld.shared.v2.u64 {%0,%1}, [%2];"
                         : "=l"(AA), "=l"(BBp) : "r"(kc_base + k * 32));
            asm volatile("ld.shared.v2.u64 {%0,%1}, [%2];"
                         : "=l"(CC), "=l"(cc) : "r"(kc_base + k * 32 + 16));
            uint64_t w, v;
            asm("fma.rn.f32x2 %0, %1, %2, %3;" : "=l"(w) : "l"(BBp), "l"(x01), "l"(CC));
            asm("fma.rn.f32x2 %0, %1, %2, %3;" : "=l"(v) : "l"(AA),  "l"(q01), "l"(w));
            float v0, v1;
            asm("mov.b64 {%0,%1}, %2;" : "=f"(v0), "=f"(v1) : "l"(v));
            float e0 = fast_ex2(v0);
            float e1 = fast_ex2(v1);
            uint64_t e01;
            asm("mov.b64 %0, {%1,%2};" : "=l"(e01) : "f"(e0), "f"(e1));
            asm("add.rn.f32x2 %0, %1, %2;"      : "=l"(den) : "l"(den), "l"(e01));
            asm("fma.rn.f32x2 %0, %1, %2, %3;"  : "=l"(cm)  : "l"(e01), "l"(cc), "l"(cm));
        }
        float den0, den1, cm0, cm1;
        asm("mov.b64 {%0,%1}, %2;" : "=f"(den0), "=f"(den1) : "l"(den));
        asm("mov.b64 {%0,%1}, %2;" : "=f"(cm0),  "=f"(cm1)  : "l"(cm));
        float2 ev;
        ev.x = fmaf(-cm0, fast_rcp(den0), xv.x);
        ev.y = fmaf(-cm1, fast_rcp(den1), xv.y);
        ep2[i] = ev;
        local += ev.x + ev.y;
    }

    // Reduce EM partial across the CTA
    const int lane = threadIdx.x & 31, warp = threadIdx.x >> 5;
#pragma unroll
    for (int off = 16; off > 0; off >>= 1)
        local += __shfl_xor_sync(0xffffffff, local, off);
    __shared__ float red[8];
    if (lane == 0) red[warp] = local;
    __syncthreads();
    if (threadIdx.x == 0) {
        float s = 0.f;
#pragma unroll
        for (int w = 0; w < 8; w++) s += red[w];
        g_EM[bd] = s * (1.0f / (float)KK);
    }
}

// ───────────────────── Kernel 2: gamma + scale + relu (fused) ─────────────────────
// One CTA per (b,d) row, 256 threads. Warp 0 recomputes this row's gamma
// from g_EM (deterministic, L2-hit), then all threads stream 784 float4's.
__global__ __launch_bounds__(256) void enc_scale_kernel(
    const float* __restrict__ fc_w,
    const float* __restrict__ fc_b,
    float* __restrict__ out)
{
    const int bd = blockIdx.x;
    const int b  = bd >> 6;
    const int d  = bd & (DD - 1);
    __shared__ float s_gm;

    if (threadIdx.x < 32) {
        const int lane = threadIdx.x;
        // 64-wide dot: 2 terms per lane
        float a = g_EM[b * DD + lane]      * fc_w[d * DD + lane]
                + g_EM[b * DD + lane + 32] * fc_w[d * DD + lane + 32];
#pragma unroll
        for (int off = 16; off > 0; off >>= 1)
            a += __shfl_xor_sync(0xffffffff, a, off);
        if (lane == 0) {
            float acc = a + fc_b[d];
            float g = fast_rcp(1.0f + fast_ex2(-acc * LOG2E));  // sigmoid
            s_gm = 1.0f + g;
        }
    }
    __syncthreads();
    const float gm = s_gm;

    float4* __restrict__ p = (float4*)(out + (size_t)bd * HW);
    const int n4 = HW / 4;   // 784
    for (int i = threadIdx.x; i < n4; i += 256) {
        float4 v = p[i];
        v.x = fmaxf(v.x * gm, 0.0f);
        v.y = fmaxf(v.y * gm, 0.0f);
        v.z = fmaxf(v.z * gm, 0.0f);
        v.w = fmaxf(v.w * gm, 0.0f);
        p[i] = v;
    }
}

extern "C" void kernel_launch(void* const* d_in, const int* in_sizes, int n_in,
                              void* d_out, int out_size) {
    const float* X    = (const float*)d_in[0];
    const float* cw   = (const float*)d_in[1];
    const float* sc   = (const float*)d_in[2];
    const float* fc_w = (const float*)d_in[3];
    const float* fc_b = (const float*)d_in[4];
    float* out = (float*)d_out;

    enc_main_kernel <<<BB * DD, 256>>>(X, cw, sc, out);
    enc_scale_kernel<<<BB * DD, 256>>>(fc_w, fc_b, out);
}